// round 10
// baseline (speedup 1.0000x reference)
#include <cuda_runtime.h>
#include <cuda_bf16.h>
#include <mma.h>
#include <cstdint>

using namespace nvcuda;

// ---------------------------------------------------------------------------
// SCM_MLP: 4 chained layers  out = relu(out @ (W*mask)^T + exp(mu+sig*z)),
// activations concatenated into d_out [B, 4H].
//
// wmma/mma.sync bf16 (family-generic ISA, survives compute_103 target),
// 3-term Markidis split  A*W ~= Ahi*Whi + Ahi*Wlo + Alo*Whi, fp32 accum.
// R10: one 512-thread CTA/SM, 128x256 tile, 3-stage cp.async pipeline with
// ONE __syncthreads per k-tile (wait -> sync -> load -> compute), LDSR=40
// (80 B rows: 16B-aligned for cp.async -- R9's LDSR=36 was the misaligned-
// address bug -- and bank-conflict-clean, proven in R8).
// ---------------------------------------------------------------------------

static constexpr int NL = 4, NB = 4096, NH = 4096;
static constexpr int BM = 128, BN = 256, BK = 32, STAGES = 3;
static constexpr int NKT = NH / BK;             // 128 k-tiles
static constexpr int LDSR = 40;                 // smem row stride (80 B, 16B-aligned)
static constexpr int SROWS = 2 * BM + 2 * BN;   // 768 rows: Ahi,Alo,Whi,Wlo
static constexpr int STAGE_E = SROWS * LDSR;    // 30720 bf16 = 61440 B
static constexpr int SMEM_BYTES = STAGES * STAGE_E * 2;   // 184320
static constexpr int FB_LD = 260;               // fp32 epilogue buffer stride
static constexpr int NTHR = 512;

// ------------------------- device scratch (.bss) ---------------------------
__device__ char g_whi[(size_t)NL * NH * NH * 2];   // 128 MiB bf16 hi
__device__ char g_wlo[(size_t)NL * NH * NH * 2];   // 128 MiB bf16 lo
__device__ char g_ahi[2][(size_t)NB * NH * 2];     // ping-pong activations hi
__device__ char g_alo[2][(size_t)NB * NH * 2];     // ping-pong activations lo

// ------------------------------ helpers ------------------------------------
__device__ __forceinline__ void cp16(void* s, const void* g) {
    uint32_t sa = (uint32_t)__cvta_generic_to_shared(s);
    asm volatile("cp.async.cg.shared.global [%0], [%1], 16;" :: "r"(sa), "l"(g));
}
#define CP_COMMIT() asm volatile("cp.async.commit_group;" ::: "memory")
#define CP_WAIT1()  asm volatile("cp.async.wait_group 1;" ::: "memory")

__device__ __forceinline__ uint32_t pack2(__nv_bfloat16 a, __nv_bfloat16 b) {
    __nv_bfloat162 t(a, b);
    return *reinterpret_cast<uint32_t*>(&t);
}

// ---------------------------------------------------------------------------
// Prepass: split W*mask into bf16 hi/lo (row-major [L][N][K]).
// ---------------------------------------------------------------------------
__global__ void wsplit_kernel(const float* __restrict__ w, const float* __restrict__ m) {
    size_t e = ((size_t)blockIdx.x * 256u + threadIdx.x) * 2u;
    float2 wv = *(const float2*)(w + e);
    float2 mv = *(const float2*)(m + e);
    float v0 = wv.x * mv.x, v1 = wv.y * mv.y;
    __nv_bfloat16 h0 = __float2bfloat16(v0), h1 = __float2bfloat16(v1);
    float l0 = v0 - __bfloat162float(h0), l1 = v1 - __bfloat162float(h1);
    *(uint32_t*)(g_whi + e * 2) = pack2(h0, h1);
    *(uint32_t*)(g_wlo + e * 2) = pack2(__float2bfloat16(l0), __float2bfloat16(l1));
}

// Prepass: split x into bf16 hi/lo (buffer 0).
__global__ void xsplit_kernel(const float* __restrict__ x) {
    size_t e = ((size_t)blockIdx.x * 256u + threadIdx.x) * 2u;
    float2 xv = *(const float2*)(x + e);
    __nv_bfloat16 h0 = __float2bfloat16(xv.x), h1 = __float2bfloat16(xv.y);
    float l0 = xv.x - __bfloat162float(h0), l1 = xv.y - __bfloat162float(h1);
    *(uint32_t*)(g_ahi[0] + e * 2) = pack2(h0, h1);
    *(uint32_t*)(g_alo[0] + e * 2) = pack2(__float2bfloat16(l0), __float2bfloat16(l1));
}

// ---------------------------------------------------------------------------
// Fused wmma GEMM + noise + relu + next-layer split.
// grid (16, 32): n0 = bx*256, m0 = by*128. 512 threads, 16 warps of 64x32.
// ---------------------------------------------------------------------------
__global__ void __launch_bounds__(NTHR, 1)
gemm_tc_kernel(int layer, int abuf, int last,
               const float* __restrict__ z, const float* __restrict__ mu,
               const float* __restrict__ sig, float* __restrict__ out) {
    extern __shared__ __nv_bfloat16 smem[];
    const int tid = threadIdx.x;
    const int wid = tid >> 5;
    const int wm = wid >> 3;          // 0..1  (warp row: 64 rows)
    const int wn = wid & 7;           // 0..7  (warp col: 32 cols)
    const int n0 = blockIdx.x * BN;
    const int m0 = blockIdx.y * BM;

    // ---- per-thread load map: 768 rows x 4 chunks = 3072, 6 per thread ----
    const char* baseAh = g_ahi[abuf] + (size_t)m0 * NH * 2;
    const char* baseAl = g_alo[abuf] + (size_t)m0 * NH * 2;
    const char* baseWh = g_whi + ((size_t)layer * NH + n0) * NH * 2;
    const char* baseWl = g_wlo + ((size_t)layer * NH + n0) * NH * 2;

    const char* gsrc[6];
    uint32_t    soff[6];   // bf16-element offset within a stage
#pragma unroll
    for (int i = 0; i < 6; i++) {
        int idx = tid + i * NTHR;      // 0..3071
        int r = idx >> 2, c = idx & 3;
        const char* b; int row;
        if (r < BM)            { b = baseAh; row = r; }
        else if (r < 2 * BM)   { b = baseAl; row = r - BM; }
        else if (r < 2*BM+BN)  { b = baseWh; row = r - 2 * BM; }
        else                   { b = baseWl; row = r - 2 * BM - BN; }
        gsrc[i] = b + (size_t)row * (NH * 2) + c * 16;
        soff[i] = (uint32_t)(r * LDSR + c * 8);
    }

    auto load_stage = [&](int slot, int kt) {
        __nv_bfloat16* st = smem + slot * STAGE_E;
        const size_t kb = (size_t)kt * 64;  // bytes along K
#pragma unroll
        for (int i = 0; i < 6; i++) cp16(st + soff[i], gsrc[i] + kb);
    };

    wmma::fragment<wmma::accumulator, 16, 16, 16, float> acc[4][2];
#pragma unroll
    for (int i = 0; i < 4; i++)
#pragma unroll
        for (int j = 0; j < 2; j++) wmma::fill_fragment(acc[i][j], 0.0f);

    // Prologue: stages 0 and 1 (one group each).
    load_stage(0, 0); CP_COMMIT();
    load_stage(1, 1); CP_COMMIT();

    int slot = 0;
    for (int kt = 0; kt < NKT; kt++) {
        // Retire group kt (newest, kt+1, may stay in flight), then barrier:
        // every thread waited -> stage kt fully visible; every warp has also
        // finished compute kt-1, so buffer (kt+2)%3 == (kt-1)%3 is reusable.
        CP_WAIT1();
        __syncthreads();
        if (kt + 2 < NKT) load_stage((slot + 2) % STAGES, kt + 2);
        CP_COMMIT();       // unconditional: keeps group count exact

        const __nv_bfloat16* st  = smem + slot * STAGE_E;
        const __nv_bfloat16* sAh = st;
        const __nv_bfloat16* sAl = st + BM * LDSR;
        const __nv_bfloat16* sWh = st + 2 * BM * LDSR;
        const __nv_bfloat16* sWl = st + (2 * BM + BN) * LDSR;

#pragma unroll
        for (int ks = 0; ks < 2; ks++) {
            // Hold all A frags (32 regs), stream B frags one j at a time.
            wmma::fragment<wmma::matrix_a, 16, 16, 16, __nv_bfloat16, wmma::row_major> aH[4], aL[4];
#pragma unroll
            for (int i = 0; i < 4; i++) {
                const int ro = (wm * 64 + i * 16) * LDSR + ks * 16;
                wmma::load_matrix_sync(aH[i], sAh + ro, LDSR);
                wmma::load_matrix_sync(aL[i], sAl + ro, LDSR);
            }
#pragma unroll
            for (int j = 0; j < 2; j++) {
                wmma::fragment<wmma::matrix_b, 16, 16, 16, __nv_bfloat16, wmma::col_major> bH, bL;
                const int ro = (wn * 32 + j * 16) * LDSR + ks * 16;
                wmma::load_matrix_sync(bH, sWh + ro, LDSR);
                wmma::load_matrix_sync(bL, sWl + ro, LDSR);
#pragma unroll
                for (int i = 0; i < 4; i++) {
                    wmma::mma_sync(acc[i][j], aH[i], bH, acc[i][j]);
                    wmma::mma_sync(acc[i][j], aH[i], bL, acc[i][j]);
                    wmma::mma_sync(acc[i][j], aL[i], bH, acc[i][j]);
                }
            }
        }
        slot = (slot + 1 == STAGES) ? 0 : slot + 1;
    }
    __syncthreads();   // all warps done with final stage before fb overwrite

    // ------------------------- epilogue ------------------------------------
    float* fb = (float*)smem;   // 128 x FB_LD fp32 = 133120 B < 184320 B
#pragma unroll
    for (int i = 0; i < 4; i++)
#pragma unroll
        for (int j = 0; j < 2; j++)
            wmma::store_matrix_sync(fb + (wm * 64 + i * 16) * FB_LD + wn * 32 + j * 16,
                                    acc[i][j], FB_LD, wmma::mem_row_major);
    __syncthreads();

    const float* zb = z + (size_t)m0 * NH + n0;
    float* ob = out + (size_t)m0 * (4 * NH) + n0;
    char* nxH = g_ahi[abuf ^ 1];
    char* nxL = g_alo[abuf ^ 1];

#pragma unroll
    for (int it = 0; it < 16; it++) {
        int idx4 = tid + it * NTHR;           // 0..8191 float4 slots
        int row  = idx4 >> 6;                 // 0..127
        int c4   = (idx4 & 63) << 2;          // 0..252

        float4 a  = *(float4*)&fb[row * FB_LD + c4];
        float4 zv = *(const float4*)(zb + (size_t)row * NH + c4);
        float4 mv = *(const float4*)(mu + n0 + c4);
        float4 sv = *(const float4*)(sig + n0 + c4);

        float v0 = fmaxf(a.x + __expf(fmaf(sv.x, zv.x, mv.x)), 0.0f);
        float v1 = fmaxf(a.y + __expf(fmaf(sv.y, zv.y, mv.y)), 0.0f);
        float v2 = fmaxf(a.z + __expf(fmaf(sv.z, zv.z, mv.z)), 0.0f);
        float v3 = fmaxf(a.w + __expf(fmaf(sv.w, zv.w, mv.w)), 0.0f);

        float4 o; o.x = v0; o.y = v1; o.z = v2; o.w = v3;
        *(float4*)(ob + (size_t)row * (4 * NH) + c4) = o;

        if (!last) {
            __nv_bfloat16 h0 = __float2bfloat16(v0), h1 = __float2bfloat16(v1);
            __nv_bfloat16 h2 = __float2bfloat16(v2), h3 = __float2bfloat16(v3);
            float l0 = v0 - __bfloat162float(h0), l1 = v1 - __bfloat162float(h1);
            float l2 = v2 - __bfloat162float(h2), l3 = v3 - __bfloat162float(h3);
            size_t off = ((size_t)(m0 + row) * NH + n0 + c4) * 2;  // bytes
            uint2 ph; ph.x = pack2(h0, h1); ph.y = pack2(h2, h3);
            uint2 pl; pl.x = pack2(__float2bfloat16(l0), __float2bfloat16(l1));
            pl.y = pack2(__float2bfloat16(l2), __float2bfloat16(l3));
            *(uint2*)(nxH + off) = ph;
            *(uint2*)(nxL + off) = pl;
        }
    }
}

// ---------------------------------------------------------------------------
// kernel_launch: prepasses + 4 chained fused GEMMs, graph-capturable.
// Inputs: x, weights, masks, mu, sigma, z. Output float32 [B, 4H].
// ---------------------------------------------------------------------------
extern "C" void kernel_launch(void* const* d_in, const int* in_sizes, int n_in,
                              void* d_out, int out_size) {
    const float* x   = (const float*)d_in[0];
    const float* w   = (const float*)d_in[1];
    const float* mk  = (const float*)d_in[2];
    const float* mu  = (const float*)d_in[3];
    const float* sg  = (const float*)d_in[4];
    const float* z   = (const float*)d_in[5];
    float*       out = (float*)d_out;

    cudaFuncSetAttribute(gemm_tc_kernel,
                         cudaFuncAttributeMaxDynamicSharedMemorySize, SMEM_BYTES);

    {   // W split
        unsigned blocks = (unsigned)(((size_t)NL * NH * NH / 2) / 256);
        wsplit_kernel<<<blocks, 256>>>(w, mk);
    }
    {   // x split
        unsigned blocks = (unsigned)(((size_t)NB * NH / 2) / 256);
        xsplit_kernel<<<blocks, 256>>>(x);
    }

    dim3 grid(NH / BN, NB / BM);  // (16, 32)
    for (int l = 0; l < NL; l++) {
        gemm_tc_kernel<<<grid, NTHR, SMEM_BYTES>>>(
            l, l & 1, (l == NL - 1) ? 1 : 0,
            z + (size_t)l * NB * NH,
            mu + (size_t)l * NH,
            sg + (size_t)l * NH,
            out + (size_t)l * NH);
    }
}

// round 11
// speedup vs baseline: 1.1481x; 1.1481x over previous
#include <cuda_runtime.h>
#include <cuda_bf16.h>
#include <mma.h>
#include <cstdint>

using namespace nvcuda;

// ---------------------------------------------------------------------------
// SCM_MLP: 4 chained layers  out = relu(out @ (W*mask)^T + exp(mu+sig*z)),
// activations concatenated into d_out [B, 4H].
//
// wmma/mma.sync bf16 (family-generic ISA, survives compute_103 target),
// 3-term Markidis split  A*W ~= Ahi*Whi + Ahi*Wlo + Alo*Whi, fp32 accum.
// R11: revert to R8's winning config (2 CTAs/SM x 256 thr, 128x128 tile,
// 2-stage cp.async, LDSR=40) -- R10 proved one fat CTA/SM loses cross-CTA
// overlap -- and cut to ONE __syncthreads per k-tile:
//   wait_group 0 -> sync -> load kt+1 -> compute kt.
// ---------------------------------------------------------------------------

static constexpr int NL = 4, NB = 4096, NH = 4096;
static constexpr int BM = 128, BN = 128, BK = 32, STAGES = 2;
static constexpr int NKT = NH / BK;            // 128 k-tiles
static constexpr int LDSR = 40;                // smem row stride in bf16 (80 B)
static constexpr int TILE_E  = 128 * LDSR;     // 5120 bf16 per tile
static constexpr int STAGE_E = 4 * TILE_E;     // Ahi,Alo,Whi,Wlo
static constexpr int SMEM_BYTES = STAGES * STAGE_E * 2;  // 81920
static constexpr int FB_LD = 132;              // fp32 epilogue buffer stride

// ------------------------- device scratch (.bss) ---------------------------
__device__ char g_whi[(size_t)NL * NH * NH * 2];   // 128 MiB bf16 hi
__device__ char g_wlo[(size_t)NL * NH * NH * 2];   // 128 MiB bf16 lo
__device__ char g_ahi[2][(size_t)NB * NH * 2];     // ping-pong activations hi
__device__ char g_alo[2][(size_t)NB * NH * 2];     // ping-pong activations lo

// ------------------------------ helpers ------------------------------------
__device__ __forceinline__ void cp16(void* s, const void* g) {
    uint32_t sa = (uint32_t)__cvta_generic_to_shared(s);
    asm volatile("cp.async.cg.shared.global [%0], [%1], 16;" :: "r"(sa), "l"(g));
}
#define CP_COMMIT() asm volatile("cp.async.commit_group;" ::: "memory")
#define CP_WAIT0()  asm volatile("cp.async.wait_group 0;" ::: "memory")

__device__ __forceinline__ uint32_t pack2(__nv_bfloat16 a, __nv_bfloat16 b) {
    __nv_bfloat162 t(a, b);
    return *reinterpret_cast<uint32_t*>(&t);
}

// ---------------------------------------------------------------------------
// Prepass: split W*mask into bf16 hi/lo (row-major [L][N][K]).
// ---------------------------------------------------------------------------
__global__ void wsplit_kernel(const float* __restrict__ w, const float* __restrict__ m) {
    size_t e = ((size_t)blockIdx.x * 256u + threadIdx.x) * 2u;
    float2 wv = *(const float2*)(w + e);
    float2 mv = *(const float2*)(m + e);
    float v0 = wv.x * mv.x, v1 = wv.y * mv.y;
    __nv_bfloat16 h0 = __float2bfloat16(v0), h1 = __float2bfloat16(v1);
    float l0 = v0 - __bfloat162float(h0), l1 = v1 - __bfloat162float(h1);
    *(uint32_t*)(g_whi + e * 2) = pack2(h0, h1);
    *(uint32_t*)(g_wlo + e * 2) = pack2(__float2bfloat16(l0), __float2bfloat16(l1));
}

// Prepass: split x into bf16 hi/lo (buffer 0).
__global__ void xsplit_kernel(const float* __restrict__ x) {
    size_t e = ((size_t)blockIdx.x * 256u + threadIdx.x) * 2u;
    float2 xv = *(const float2*)(x + e);
    __nv_bfloat16 h0 = __float2bfloat16(xv.x), h1 = __float2bfloat16(xv.y);
    float l0 = xv.x - __bfloat162float(h0), l1 = xv.y - __bfloat162float(h1);
    *(uint32_t*)(g_ahi[0] + e * 2) = pack2(h0, h1);
    *(uint32_t*)(g_alo[0] + e * 2) = pack2(__float2bfloat16(l0), __float2bfloat16(l1));
}

// ---------------------------------------------------------------------------
// Fused wmma GEMM + noise + relu + next-layer split.
// grid (32, 32): n0 = bx*128, m0 = by*128. 256 threads, 8 warps of 64x32.
// ---------------------------------------------------------------------------
__global__ void __launch_bounds__(256, 2)
gemm_tc_kernel(int layer, int abuf, int last,
               const float* __restrict__ z, const float* __restrict__ mu,
               const float* __restrict__ sig, float* __restrict__ out) {
    extern __shared__ __nv_bfloat16 smem[];
    const int tid = threadIdx.x;
    const int wid = tid >> 5;
    const int wm = wid >> 2;          // 0..1  (warp row: 64 rows)
    const int wn = wid & 3;           // 0..3  (warp col: 32 cols)
    const int n0 = blockIdx.x * BN;
    const int m0 = blockIdx.y * BM;

    const char* src[4];
    src[0] = g_ahi[abuf] + (size_t)m0 * NH * 2;
    src[1] = g_alo[abuf] + (size_t)m0 * NH * 2;
    src[2] = g_whi + ((size_t)layer * NH + n0) * NH * 2;
    src[3] = g_wlo + ((size_t)layer * NH + n0) * NH * 2;

    // Per-thread load slots: 512 16B-chunks per tile, 2 per thread per tile.
    const int r_0 = tid >> 2,         c_0 = tid & 3;
    const int r_1 = (tid + 256) >> 2, c_1 = (tid + 256) & 3;

    auto load_stage = [&](int slot, int kt) {
        __nv_bfloat16* st = smem + slot * STAGE_E;
        const size_t kb = (size_t)kt * 64;  // byte offset along K
#pragma unroll
        for (int t = 0; t < 4; t++) {
            cp16(st + t * TILE_E + r_0 * LDSR + c_0 * 8,
                 src[t] + (size_t)r_0 * (NH * 2) + kb + c_0 * 16);
            cp16(st + t * TILE_E + r_1 * LDSR + c_1 * 8,
                 src[t] + (size_t)r_1 * (NH * 2) + kb + c_1 * 16);
        }
    };

    wmma::fragment<wmma::accumulator, 16, 16, 16, float> acc[4][2];
#pragma unroll
    for (int i = 0; i < 4; i++)
#pragma unroll
        for (int j = 0; j < 2; j++) wmma::fill_fragment(acc[i][j], 0.0f);

    // Prologue: stage 0 (group g0).
    load_stage(0, 0); CP_COMMIT();

    for (int kt = 0; kt < NKT; kt++) {
        // Newest committed group at this point is g_kt (issued last iter):
        // retire everything per-thread, then one barrier gives (a) cross-
        // thread visibility of stage kt and (b) all warps done compute kt-1,
        // so buffer (kt+1)&1 is safe to overwrite below.
        CP_WAIT0();
        __syncthreads();
        if (kt + 1 < NKT) { load_stage((kt + 1) & 1, kt + 1); CP_COMMIT(); }

        const __nv_bfloat16* st = smem + (kt & 1) * STAGE_E;
        const __nv_bfloat16* sAh = st;
        const __nv_bfloat16* sAl = st + TILE_E;
        const __nv_bfloat16* sWh = st + 2 * TILE_E;
        const __nv_bfloat16* sWl = st + 3 * TILE_E;

#pragma unroll
        for (int ks = 0; ks < 2; ks++) {
            // Hold all A frags (32 regs), stream B frags one j at a time.
            wmma::fragment<wmma::matrix_a, 16, 16, 16, __nv_bfloat16, wmma::row_major> aH[4], aL[4];
#pragma unroll
            for (int i = 0; i < 4; i++) {
                const int ro = (wm * 64 + i * 16) * LDSR + ks * 16;
                wmma::load_matrix_sync(aH[i], sAh + ro, LDSR);
                wmma::load_matrix_sync(aL[i], sAl + ro, LDSR);
            }
#pragma unroll
            for (int j = 0; j < 2; j++) {
                wmma::fragment<wmma::matrix_b, 16, 16, 16, __nv_bfloat16, wmma::col_major> bH, bL;
                const int ro = (wn * 32 + j * 16) * LDSR + ks * 16;
                wmma::load_matrix_sync(bH, sWh + ro, LDSR);
                wmma::load_matrix_sync(bL, sWl + ro, LDSR);
#pragma unroll
                for (int i = 0; i < 4; i++) {
                    wmma::mma_sync(acc[i][j], aH[i], bH, acc[i][j]);
                    wmma::mma_sync(acc[i][j], aH[i], bL, acc[i][j]);
                    wmma::mma_sync(acc[i][j], aL[i], bH, acc[i][j]);
                }
            }
        }
    }
    __syncthreads();   // all warps done with final stage before fb overwrite

    // ------------------------- epilogue ------------------------------------
    float* fb = (float*)smem;   // 128 x FB_LD fp32 (67.6 KB < 80 KB)
#pragma unroll
    for (int i = 0; i < 4; i++)
#pragma unroll
        for (int j = 0; j < 2; j++)
            wmma::store_matrix_sync(fb + (wm * 64 + i * 16) * FB_LD + wn * 32 + j * 16,
                                    acc[i][j], FB_LD, wmma::mem_row_major);
    __syncthreads();

    const float* zb = z + (size_t)m0 * NH + n0;
    float* ob = out + (size_t)m0 * (4 * NH) + n0;
    char* nxH = g_ahi[abuf ^ 1];
    char* nxL = g_alo[abuf ^ 1];

#pragma unroll
    for (int it = 0; it < 16; it++) {
        int idx4 = tid + it * 256;            // 0..4095 float4 slots
        int row  = idx4 >> 5;                 // 0..127
        int c4   = (idx4 & 31) << 2;          // 0..124

        float4 a  = *(float4*)&fb[row * FB_LD + c4];
        float4 zv = *(const float4*)(zb + (size_t)row * NH + c4);
        float4 mv = *(const float4*)(mu + n0 + c4);
        float4 sv = *(const float4*)(sig + n0 + c4);

        float v0 = fmaxf(a.x + __expf(fmaf(sv.x, zv.x, mv.x)), 0.0f);
        float v1 = fmaxf(a.y + __expf(fmaf(sv.y, zv.y, mv.y)), 0.0f);
        float v2 = fmaxf(a.z + __expf(fmaf(sv.z, zv.z, mv.z)), 0.0f);
        float v3 = fmaxf(a.w + __expf(fmaf(sv.w, zv.w, mv.w)), 0.0f);

        float4 o; o.x = v0; o.y = v1; o.z = v2; o.w = v3;
        *(float4*)(ob + (size_t)row * (4 * NH) + c4) = o;

        if (!last) {
            __nv_bfloat16 h0 = __float2bfloat16(v0), h1 = __float2bfloat16(v1);
            __nv_bfloat16 h2 = __float2bfloat16(v2), h3 = __float2bfloat16(v3);
            float l0 = v0 - __bfloat162float(h0), l1 = v1 - __bfloat162float(h1);
            float l2 = v2 - __bfloat162float(h2), l3 = v3 - __bfloat162float(h3);
            size_t off = ((size_t)(m0 + row) * NH + n0 + c4) * 2;  // bytes
            uint2 ph; ph.x = pack2(h0, h1); ph.y = pack2(h2, h3);
            uint2 pl; pl.x = pack2(__float2bfloat16(l0), __float2bfloat16(l1));
            pl.y = pack2(__float2bfloat16(l2), __float2bfloat16(l3));
            *(uint2*)(nxH + off) = ph;
            *(uint2*)(nxL + off) = pl;
        }
    }
}

// ---------------------------------------------------------------------------
// kernel_launch: prepasses + 4 chained fused GEMMs, graph-capturable.
// Inputs: x, weights, masks, mu, sigma, z. Output float32 [B, 4H].
// ---------------------------------------------------------------------------
extern "C" void kernel_launch(void* const* d_in, const int* in_sizes, int n_in,
                              void* d_out, int out_size) {
    const float* x   = (const float*)d_in[0];
    const float* w   = (const float*)d_in[1];
    const float* mk  = (const float*)d_in[2];
    const float* mu  = (const float*)d_in[3];
    const float* sg  = (const float*)d_in[4];
    const float* z   = (const float*)d_in[5];
    float*       out = (float*)d_out;

    cudaFuncSetAttribute(gemm_tc_kernel,
                         cudaFuncAttributeMaxDynamicSharedMemorySize, SMEM_BYTES);

    {   // W split
        unsigned blocks = (unsigned)(((size_t)NL * NH * NH / 2) / 256);
        wsplit_kernel<<<blocks, 256>>>(w, mk);
    }
    {   // x split
        unsigned blocks = (unsigned)(((size_t)NB * NH / 2) / 256);
        xsplit_kernel<<<blocks, 256>>>(x);
    }

    dim3 grid(NH / BN, NB / BM);  // (32, 32)
    for (int l = 0; l < NL; l++) {
        gemm_tc_kernel<<<grid, 256, SMEM_BYTES>>>(
            l, l & 1, (l == NL - 1) ? 1 : 0,
            z + (size_t)l * NB * NH,
            mu + (size_t)l * NH,
            sg + (size_t)l * NH,
            out + (size_t)l * NH);
    }
}

// round 13
// speedup vs baseline: 1.1827x; 1.0302x over previous
#include <cuda_runtime.h>
#include <cuda_bf16.h>
#include <mma.h>
#include <cstdint>

using namespace nvcuda;

// ---------------------------------------------------------------------------
// SCM_MLP: 4 chained layers  out = relu(out @ (W*mask)^T + exp(mu+sig*z)),
// activations concatenated into d_out [B, 4H].
//
// wmma/mma.sync bf16 (family-generic ISA, survives compute_103 target),
// 3-term Markidis split  A*W ~= Ahi*Whi + Ahi*Wlo + Alo*Whi, fp32 accum.
// R12: 2 CTAs/SM (R8 base) + THREE stages by unpadding the W tiles
// (LDSR_W=32; A stays LDSR=40). Single barrier per k-tile, cutlass order:
//   wait_group 1 -> sync -> load kt+2 -> compute kt   (depth-2 prefetch).
// ---------------------------------------------------------------------------

static constexpr int NL = 4, NB = 4096, NH = 4096;
static constexpr int BM = 128, BN = 128, BK = 32, STAGES = 3;
static constexpr int NKT = NH / BK;            // 128 k-tiles
static constexpr int LDSA = 40;                // A smem stride (80 B, padded)
static constexpr int LDSW = 32;                // W smem stride (64 B, raw)
static constexpr int A_T_E = 128 * LDSA;       // 5120 els per A tile
static constexpr int W_T_E = 128 * LDSW;       // 4096 els per W tile
static constexpr int OFF_AL = A_T_E;           // 5120
static constexpr int OFF_WH = 2 * A_T_E;       // 10240
static constexpr int OFF_WL = 2 * A_T_E + W_T_E;  // 14336
static constexpr int STAGE_E = 2 * A_T_E + 2 * W_T_E;     // 18432 els = 36864 B
static constexpr int SMEM_BYTES = STAGES * STAGE_E * 2;   // 110592
static constexpr int FB_LD = 132;              // fp32 epilogue buffer stride

// ------------------------- device scratch (.bss) ---------------------------
__device__ char g_whi[(size_t)NL * NH * NH * 2];   // 128 MiB bf16 hi
__device__ char g_wlo[(size_t)NL * NH * NH * 2];   // 128 MiB bf16 lo
__device__ char g_ahi[2][(size_t)NB * NH * 2];     // ping-pong activations hi
__device__ char g_alo[2][(size_t)NB * NH * 2];     // ping-pong activations lo

// ------------------------------ helpers ------------------------------------
__device__ __forceinline__ void cp16(void* s, const void* g) {
    uint32_t sa = (uint32_t)__cvta_generic_to_shared(s);
    asm volatile("cp.async.cg.shared.global [%0], [%1], 16;" :: "r"(sa), "l"(g));
}
#define CP_COMMIT() asm volatile("cp.async.commit_group;" ::: "memory")
#define CP_WAIT1()  asm volatile("cp.async.wait_group 1;" ::: "memory")

__device__ __forceinline__ uint32_t pack2(__nv_bfloat16 a, __nv_bfloat16 b) {
    __nv_bfloat162 t(a, b);
    return *reinterpret_cast<uint32_t*>(&t);
}

// ---------------------------------------------------------------------------
// Prepass: split W*mask into bf16 hi/lo (row-major [L][N][K]).
// ---------------------------------------------------------------------------
__global__ void wsplit_kernel(const float* __restrict__ w, const float* __restrict__ m) {
    size_t e = ((size_t)blockIdx.x * 256u + threadIdx.x) * 2u;
    float2 wv = *(const float2*)(w + e);
    float2 mv = *(const float2*)(m + e);
    float v0 = wv.x * mv.x, v1 = wv.y * mv.y;
    __nv_bfloat16 h0 = __float2bfloat16(v0), h1 = __float2bfloat16(v1);
    float l0 = v0 - __bfloat162float(h0), l1 = v1 - __bfloat162float(h1);
    *(uint32_t*)(g_whi + e * 2) = pack2(h0, h1);
    *(uint32_t*)(g_wlo + e * 2) = pack2(__float2bfloat16(l0), __float2bfloat16(l1));
}

// Prepass: split x into bf16 hi/lo (buffer 0).
__global__ void xsplit_kernel(const float* __restrict__ x) {
    size_t e = ((size_t)blockIdx.x * 256u + threadIdx.x) * 2u;
    float2 xv = *(const float2*)(x + e);
    __nv_bfloat16 h0 = __float2bfloat16(xv.x), h1 = __float2bfloat16(xv.y);
    float l0 = xv.x - __bfloat162float(h0), l1 = xv.y - __bfloat162float(h1);
    *(uint32_t*)(g_ahi[0] + e * 2) = pack2(h0, h1);
    *(uint32_t*)(g_alo[0] + e * 2) = pack2(__float2bfloat16(l0), __float2bfloat16(l1));
}

// ---------------------------------------------------------------------------
// Fused wmma GEMM + noise + relu + next-layer split.
// grid (32, 32): n0 = bx*128, m0 = by*128. 256 threads, 8 warps of 64x32.
// ---------------------------------------------------------------------------
__global__ void __launch_bounds__(256, 2)
gemm_tc_kernel(int layer, int abuf, int last,
               const float* __restrict__ z, const float* __restrict__ mu,
               const float* __restrict__ sig, float* __restrict__ out) {
    extern __shared__ __nv_bfloat16 smem[];
    const int tid = threadIdx.x;
    const int wid = tid >> 5;
    const int wm = wid >> 2;          // 0..1  (warp row: 64 rows)
    const int wn = wid & 3;           // 0..3  (warp col: 32 cols)
    const int n0 = blockIdx.x * BN;
    const int m0 = blockIdx.y * BM;

    const char* srcAh = g_ahi[abuf] + (size_t)m0 * NH * 2;
    const char* srcAl = g_alo[abuf] + (size_t)m0 * NH * 2;
    const char* srcWh = g_whi + ((size_t)layer * NH + n0) * NH * 2;
    const char* srcWl = g_wlo + ((size_t)layer * NH + n0) * NH * 2;

    // Per-thread load slots: 512 16B-chunks per tile, 2 per thread per tile.
    const int r_0 = tid >> 2;          // rows 0..63
    const int r_1 = r_0 + 64;          // rows 64..127
    const int c_0 = tid & 3;           // 16B chunk within the 64B K-slice

    auto load_stage = [&](int slot, int kt) {
        __nv_bfloat16* st = smem + slot * STAGE_E;
        const size_t kb = (size_t)kt * 64;  // byte offset along K
        // A tiles: stride LDSA
        cp16(st + r_0 * LDSA + c_0 * 8,           srcAh + (size_t)r_0 * (NH*2) + kb + c_0 * 16);
        cp16(st + r_1 * LDSA + c_0 * 8,           srcAh + (size_t)r_1 * (NH*2) + kb + c_0 * 16);
        cp16(st + OFF_AL + r_0 * LDSA + c_0 * 8,  srcAl + (size_t)r_0 * (NH*2) + kb + c_0 * 16);
        cp16(st + OFF_AL + r_1 * LDSA + c_0 * 8,  srcAl + (size_t)r_1 * (NH*2) + kb + c_0 * 16);
        // W tiles: stride LDSW (raw 64 B rows)
        cp16(st + OFF_WH + r_0 * LDSW + c_0 * 8,  srcWh + (size_t)r_0 * (NH*2) + kb + c_0 * 16);
        cp16(st + OFF_WH + r_1 * LDSW + c_0 * 8,  srcWh + (size_t)r_1 * (NH*2) + kb + c_0 * 16);
        cp16(st + OFF_WL + r_0 * LDSW + c_0 * 8,  srcWl + (size_t)r_0 * (NH*2) + kb + c_0 * 16);
        cp16(st + OFF_WL + r_1 * LDSW + c_0 * 8,  srcWl + (size_t)r_1 * (NH*2) + kb + c_0 * 16);
    };

    wmma::fragment<wmma::accumulator, 16, 16, 16, float> acc[4][2];
#pragma unroll
    for (int i = 0; i < 4; i++)
#pragma unroll
        for (int j = 0; j < 2; j++) wmma::fill_fragment(acc[i][j], 0.0f);

    // Prologue: stages 0 and 1 (one group each).
    load_stage(0, 0); CP_COMMIT();
    load_stage(1, 1); CP_COMMIT();

    int slot = 0;
    for (int kt = 0; kt < NKT; kt++) {
        // Newest group here is g_{kt+1}: wait_group 1 retires g_kt (stage kt
        // resident per-thread), then the barrier gives cross-thread
        // visibility AND guarantees all warps finished compute kt-1, so
        // buffer (kt+2)%3 == (kt-1)%3 is free to overwrite.
        CP_WAIT1();
        __syncthreads();
        if (kt + 2 < NKT) load_stage((slot + 2) % STAGES, kt + 2);
        CP_COMMIT();   // unconditional: empty group keeps the count exact

        const __nv_bfloat16* st  = smem + slot * STAGE_E;
        const __nv_bfloat16* sAh = st;
        const __nv_bfloat16* sAl = st + OFF_AL;
        const __nv_bfloat16* sWh = st + OFF_WH;
        const __nv_bfloat16* sWl = st + OFF_WL;

#pragma unroll
        for (int ks = 0; ks < 2; ks++) {
            // Hold all A frags (32 regs), stream B frags one j at a time.
            wmma::fragment<wmma::matrix_a, 16, 16, 16, __nv_bfloat16, wmma::row_major> aH[4], aL[4];
#pragma unroll
            for (int i = 0; i < 4; i++) {
                const int ro = (wm * 64 + i * 16) * LDSA + ks * 16;
                wmma::load_matrix_sync(aH[i], sAh + ro, LDSA);
                wmma::load_matrix_sync(aL[i], sAl + ro, LDSA);
            }
#pragma unroll
            for (int j = 0; j < 2; j++) {
                wmma::fragment<wmma::matrix_b, 16, 16, 16, __nv_bfloat16, wmma::col_major> bH, bL;
                const int ro = (wn * 32 + j * 16) * LDSW + ks * 16;
                wmma::load_matrix_sync(bH, sWh + ro, LDSW);
                wmma::load_matrix_sync(bL, sWl + ro, LDSW);
#pragma unroll
                for (int i = 0; i < 4; i++) {
                    wmma::mma_sync(acc[i][j], aH[i], bH, acc[i][j]);
                    wmma::mma_sync(acc[i][j], aH[i], bL, acc[i][j]);
                    wmma::mma_sync(acc[i][j], aL[i], bH, acc[i][j]);
                }
            }
        }
        slot = (slot + 1 == STAGES) ? 0 : slot + 1;
    }
    __syncthreads();   // all warps done with final stage before fb overwrite

    // ------------------------- epilogue ------------------------------------
    float* fb = (float*)smem;   // 128 x FB_LD fp32 (67.6 KB < 108 KB)
#pragma unroll
    for (int i = 0; i < 4; i++)
#pragma unroll
        for (int j = 0; j < 2; j++)
            wmma::store_matrix_sync(fb + (wm * 64 + i * 16) * FB_LD + wn * 32 + j * 16,
                                    acc[i][j], FB_LD, wmma::mem_row_major);
    __syncthreads();

    const float* zb = z + (size_t)m0 * NH + n0;
    float* ob = out + (size_t)m0 * (4 * NH) + n0;
    char* nxH = g_ahi[abuf ^ 1];
    char* nxL = g_alo[abuf ^ 1];

#pragma unroll
    for (int it = 0; it < 16; it++) {
        int idx4 = tid + it * 256;            // 0..4095 float4 slots
        int row  = idx4 >> 5;                 // 0..127
        int c4   = (idx4 & 31) << 2;          // 0..124

        float4 a  = *(float4*)&fb[row * FB_LD + c4];
        float4 zv = *(const float4*)(zb + (size_t)row * NH + c4);
        float4 mv = *(const float4*)(mu + n0 + c4);
        float4 sv = *(const float4*)(sig + n0 + c4);

        float v0 = fmaxf(a.x + __expf(fmaf(sv.x, zv.x, mv.x)), 0.0f);
        float v1 = fmaxf(a.y + __expf(fmaf(sv.y, zv.y, mv.y)), 0.0f);
        float v2 = fmaxf(a.z + __expf(fmaf(sv.z, zv.z, mv.z)), 0.0f);
        float v3 = fmaxf(a.w + __expf(fmaf(sv.w, zv.w, mv.w)), 0.0f);

        float4 o; o.x = v0; o.y = v1; o.z = v2; o.w = v3;
        *(float4*)(ob + (size_t)row * (4 * NH) + c4) = o;

        if (!last) {
            __nv_bfloat16 h0 = __float2bfloat16(v0), h1 = __float2bfloat16(v1);
            __nv_bfloat16 h2 = __float2bfloat16(v2), h3 = __float2bfloat16(v3);
            float l0 = v0 - __bfloat162float(h0), l1 = v1 - __bfloat162float(h1);
            float l2 = v2 - __bfloat162float(h2), l3 = v3 - __bfloat162float(h3);
            size_t off = ((size_t)(m0 + row) * NH + n0 + c4) * 2;  // bytes
            uint2 ph; ph.x = pack2(h0, h1); ph.y = pack2(h2, h3);
            uint2 pl; pl.x = pack2(__float2bfloat16(l0), __float2bfloat16(l1));
            pl.y = pack2(__float2bfloat16(l2), __float2bfloat16(l3));
            *(uint2*)(nxH + off) = ph;
            *(uint2*)(nxL + off) = pl;
        }
    }
}

// ---------------------------------------------------------------------------
// kernel_launch: prepasses + 4 chained fused GEMMs, graph-capturable.
// Inputs: x, weights, masks, mu, sigma, z. Output float32 [B, 4H].
// ---------------------------------------------------------------------------
extern "C" void kernel_launch(void* const* d_in, const int* in_sizes, int n_in,
                              void* d_out, int out_size) {
    const float* x   = (const float*)d_in[0];
    const float* w   = (const float*)d_in[1];
    const float* mk  = (const float*)d_in[2];
    const float* mu  = (const float*)d_in[3];
    const float* sg  = (const float*)d_in[4];
    const float* z   = (const float*)d_in[5];
    float*       out = (float*)d_out;

    cudaFuncSetAttribute(gemm_tc_kernel,
                         cudaFuncAttributeMaxDynamicSharedMemorySize, SMEM_BYTES);

    {   // W split
        unsigned blocks = (unsigned)(((size_t)NL * NH * NH / 2) / 256);
        wsplit_kernel<<<blocks, 256>>>(w, mk);
    }
    {   // x split
        unsigned blocks = (unsigned)(((size_t)NB * NH / 2) / 256);
        xsplit_kernel<<<blocks, 256>>>(x);
    }

    dim3 grid(NH / BN, NB / BM);  // (32, 32)
    for (int l = 0; l < NL; l++) {
        gemm_tc_kernel<<<grid, 256, SMEM_BYTES>>>(
            l, l & 1, (l == NL - 1) ? 1 : 0,
            z + (size_t)l * NB * NH,
            mu + (size_t)l * NH,
            sg + (size_t)l * NH,
            out + (size_t)l * NH);
    }
}